// round 1
// baseline (speedup 1.0000x reference)
#include <cuda_runtime.h>
#include <math.h>

// RandomLowRes2D: per-image Gaussian blur + down/up linear resample along one axis.
// 64 images of 512x512 fp32. inputs: x[64*512*512], resolution[64], axis[64](int), gap[64].

#define HDIM   512
#define TW     32          // lanes (cross-axis) per CTA
#define PITCH  33          // smem pitch (conflict-free for both access orders)
#define RAD    15
#define NW     (2*RAD+1)   // 31 taps
#define NT     512         // threads per CTA
#define UN     8           // pos rows per blur task (register sliding window)

__global__ __launch_bounds__(NT, 1)
void lowres_kernel(const float* __restrict__ x,
                   const float* __restrict__ resolution,
                   const int*   __restrict__ axis,
                   const float* __restrict__ gap,
                   float* __restrict__ out)
{
    extern __shared__ float smem[];
    float* A = smem;                   // [HDIM][PITCH]
    float* S = smem + HDIM * PITCH;    // [HDIM][PITCH]
    __shared__ float w[NW];
    __shared__ float wsum;

    const int img  = blockIdx.y;       // 0..63
    const int tile = blockIdx.x;       // 0..15
    const int tid  = threadIdx.x;

    const float res = resolution[img];
    const int   ax  = axis[img];
    // SIG_PER_FWHM = 1/sqrt(8 ln 2)
    const float sig = fmaxf(res * gap[img] * 0.42466090014400953f, 1e-6f);

    // ---- Gaussian weights (normalized) ----
    if (tid < NW) {
        float off = (float)(tid - RAD);
        float e = off / sig;
        w[tid] = expf(-0.5f * e * e);
    }
    __syncthreads();
    if (tid == 0) {
        float s = 0.f;
        #pragma unroll
        for (int k = 0; k < NW; k++) s += w[k];
        wsum = s;
    }
    __syncthreads();
    if (tid < NW) w[tid] = w[tid] / wsum;
    __syncthreads();

    const size_t ibase = (size_t)img * HDIM * HDIM;
    const float* ip = x + ibase;
    float*       op = out + ibase;
    const int base = tile * TW;        // column base (ax==0) or row base (ax==1)

    // ---- Load: gmem -> smem A[pos][lane], coalesced for either axis ----
    if (ax == 0) {
        // processed axis = rows (H). lane = column (contiguous in gmem).
        for (int idx = tid; idx < HDIM * TW; idx += NT) {
            int lane = idx & (TW - 1);
            int pos  = idx >> 5;
            A[pos * PITCH + lane] = ip[pos * HDIM + base + lane];
        }
    } else {
        // processed axis = columns (W, contiguous in gmem). lane = row.
        for (int idx = tid; idx < HDIM * TW; idx += NT) {
            int pos  = idx & (HDIM - 1);   // contiguous gmem, padded-smem stride 33
            int lane = idx >> 9;
            A[pos * PITCH + lane] = ip[(base + lane) * HDIM + pos];
        }
    }
    __syncthreads();

    // ---- Blur along pos (31 taps, symmetric boundary), sliding register window ----
    for (int task = tid; task < (HDIM / UN) * TW; task += NT) {
        int lane = task & (TW - 1);
        int p0   = (task >> 5) * UN;
        float win[UN + NW - 1];
        #pragma unroll
        for (int j = 0; j < UN + NW - 1; j++) {
            int t = p0 - RAD + j;
            t = (t < 0) ? (-1 - t) : t;                 // symmetric (edge-inclusive)
            t = (t >= HDIM) ? (2 * HDIM - 1 - t) : t;
            win[j] = A[t * PITCH + lane];
        }
        #pragma unroll
        for (int u = 0; u < UN; u++) {
            float acc = 0.f;
            #pragma unroll
            for (int k = 0; k < NW; k++) acc += w[k] * win[u + k];
            S[(p0 + u) * PITCH + lane] = acc;
        }
    }
    __syncthreads();

    // ---- Downsample (factor 1/res, anchor 'f'): S -> A (reused) ----
    const int n_low = (int)fmaxf(floorf(512.0f / res), 1.0f);
    for (int idx = tid; idx < n_low * TW; idx += NT) {
        int lane = idx & (TW - 1);
        int j    = idx >> 5;
        float pos = fminf(fmaxf((float)j * res, 0.0f), 511.0f);
        float lof = floorf(pos);
        float fr  = pos - lof;
        int lo = (int)lof;
        int hi = min(lo + 1, HDIM - 1);
        A[j * PITCH + lane] = S[lo * PITCH + lane] * (1.0f - fr)
                            + S[hi * PITCH + lane] * fr;
    }
    __syncthreads();

    // ---- Upsample (factor res, anchor 'f') + coalesced store ----
    const float nl1 = (float)(n_low - 1);
    if (ax == 0) {
        for (int idx = tid; idx < HDIM * TW; idx += NT) {
            int lane = idx & (TW - 1);
            int pos  = idx >> 5;
            float p2  = fminf(fmaxf((float)pos / res, 0.0f), nl1);
            float lof = floorf(p2);
            float fr  = p2 - lof;
            int lo = min((int)lof, n_low - 1);
            int hi = min(lo + 1, n_low - 1);
            op[pos * HDIM + base + lane] =
                A[lo * PITCH + lane] * (1.0f - fr) + A[hi * PITCH + lane] * fr;
        }
    } else {
        for (int idx = tid; idx < HDIM * TW; idx += NT) {
            int pos  = idx & (HDIM - 1);
            int lane = idx >> 9;
            float p2  = fminf(fmaxf((float)pos / res, 0.0f), nl1);
            float lof = floorf(p2);
            float fr  = p2 - lof;
            int lo = min((int)lof, n_low - 1);
            int hi = min(lo + 1, n_low - 1);
            op[(base + lane) * HDIM + pos] =
                A[lo * PITCH + lane] * (1.0f - fr) + A[hi * PITCH + lane] * fr;
        }
    }
}

extern "C" void kernel_launch(void* const* d_in, const int* in_sizes, int n_in,
                              void* d_out, int out_size)
{
    const float* x   = (const float*)d_in[0];
    const float* res = (const float*)d_in[1];
    const int*   ax  = (const int*)d_in[2];
    const float* gp  = (const float*)d_in[3];
    float* out = (float*)d_out;

    const int n_img = in_sizes[1];              // B*C = 64
    const size_t smem = (size_t)2 * HDIM * PITCH * sizeof(float);  // 135168 B

    cudaFuncSetAttribute(lowres_kernel,
                         cudaFuncAttributeMaxDynamicSharedMemorySize, (int)smem);

    dim3 grid(HDIM / TW, n_img);                // 16 x 64 = 1024 CTAs
    lowres_kernel<<<grid, NT, smem>>>(x, res, ax, gp, out);
}